// round 2
// baseline (speedup 1.0000x reference)
#include <cuda_runtime.h>
#include <cstdint>

// Problem constants
#define B_ 512
#define F_ 1180
#define A_ 50
#define C_ 1024
#define W_ 19            // ceil(1180 / 64) u64 words per feature-bitmask
#define NCLAUSE (A_*C_)  // 51200
#define TA_ROWS (NCLAUSE*2)

// Scratch (allocation-free rule: __device__ globals)
__device__ unsigned long long g_pos[NCLAUSE * W_];   // 7.78 MB
__device__ unsigned long long g_neg[NCLAUSE * W_];   // 7.78 MB
__device__ unsigned long long g_x[B_ * W_];          // 77.8 KB

// ---------------------------------------------------------------------------
// Pack ta_state [A,C,2,F] fp32 -> per-clause include bitmasks.
// One warp per (a,c,pol) row. Bit permutation within a u64 word:
//   lane reads float2 at f = w*64 + 2*lane; bit lane  <- (f0 > 16),
//   bit 32+lane <- (f1 > 16). The x pack uses the SAME permutation, so
//   (pos & ~x) etc. are permutation-invariant.
// ---------------------------------------------------------------------------
__global__ void pack_ta_kernel(const float* __restrict__ ta) {
    int warp = (blockIdx.x * blockDim.x + threadIdx.x) >> 5;
    int lane = threadIdx.x & 31;
    if (warp >= TA_ROWS) return;
    const float* row = ta + (size_t)warp * F_;
    unsigned long long* out =
        ((warp & 1) ? g_neg : g_pos) + (size_t)(warp >> 1) * W_;
#pragma unroll
    for (int w = 0; w < W_; ++w) {
        int i0 = w * 64 + 2 * lane;
        float f0 = -1e9f, f1 = -1e9f;
        if (i0 + 1 < F_) {                      // F_ even -> pairs never split
            float2 v = *reinterpret_cast<const float2*>(row + i0);
            f0 = v.x; f1 = v.y;
        }
        unsigned b0 = __ballot_sync(0xffffffffu, f0 > 16.0f);
        unsigned b1 = __ballot_sync(0xffffffffu, f1 > 16.0f);
        if (lane == 0)
            out[w] = (unsigned long long)b0 | ((unsigned long long)b1 << 32);
    }
}

// Pack binary_features [B,F] fp32 (0/1) with the same permutation.
__global__ void pack_x_kernel(const float* __restrict__ x) {
    int warp = (blockIdx.x * blockDim.x + threadIdx.x) >> 5;
    int lane = threadIdx.x & 31;
    if (warp >= B_) return;
    const float* row = x + (size_t)warp * F_;
    unsigned long long* out = g_x + (size_t)warp * W_;
#pragma unroll
    for (int w = 0; w < W_; ++w) {
        int i0 = w * 64 + 2 * lane;
        float f0 = -1.0f, f1 = -1.0f;
        if (i0 + 1 < F_) {
            float2 v = *reinterpret_cast<const float2*>(row + i0);
            f0 = v.x; f1 = v.y;
        }
        unsigned b0 = __ballot_sync(0xffffffffu, f0 > 0.5f);
        unsigned b1 = __ballot_sync(0xffffffffu, f1 > 0.5f);
        if (lane == 0)
            out[w] = (unsigned long long)b0 | ((unsigned long long)b1 << 32);
    }
}

// ---------------------------------------------------------------------------
// Eval: block = (class a, chunk of 64 batch rows). 8 warps; warp takes
// clauses c = warp, warp+8, ... Each lane evaluates one batch row against
// the warp's current clause. Word 0 rejects ~all clauses; survivors take
// the exact full-word path (still exact for any data).
// ---------------------------------------------------------------------------
__global__ __launch_bounds__(256) void eval_kernel(
    const float* __restrict__ sign,
    const int*   __restrict__ Tptr,
    float*       __restrict__ out)
{
    __shared__ unsigned long long sx[64 * W_];   // 9728 B
    __shared__ float sv[8][64];                  // 2048 B

    const int a  = blockIdx.x;
    const int b0 = blockIdx.y * 64;
    const int tid = threadIdx.x;

    for (int i = tid; i < 64 * W_; i += 256) {
        int b = i / W_, w = i - b * W_;
        sx[i] = g_x[(size_t)(b0 + b) * W_ + w];
    }
    __syncthreads();

    const int warp = tid >> 5, lane = tid & 31;
    float v0 = 0.f, v1 = 0.f;

    for (int c = warp; c < C_; c += 8) {
        const size_t base = ((size_t)a * C_ + c) * W_;
        const unsigned long long p0 = g_pos[base];
        const unsigned long long n0 = g_neg[base];
        const float sg = sign[a * C_ + c];
#pragma unroll
        for (int half = 0; half < 2; ++half) {
            const int bl = half * 32 + lane;
            const unsigned long long x0 = sx[bl * W_];
            unsigned long long viol = (p0 & ~x0) | (n0 & x0);
            bool alive = (viol == 0ull);
            if (__ballot_sync(0xffffffffu, alive)) {
                if (alive) {
                    for (int w = 1; w < W_; ++w) {
                        const unsigned long long xw = sx[bl * W_ + w];
                        const unsigned long long vw =
                            (g_pos[base + w] & ~xw) | (g_neg[base + w] & xw);
                        if (vw) { alive = false; break; }
                    }
                }
            }
            const float add = alive ? sg : 0.f;
            if (half == 0) v0 += add; else v1 += add;
        }
    }

    sv[warp][lane]      = v0;
    sv[warp][32 + lane] = v1;
    __syncthreads();

    if (tid < 64) {
        float s = 0.f;
#pragma unroll
        for (int w = 0; w < 8; ++w) s += sv[w][tid];
        // T is a scalar; int32 is expected, fall back to float32 bits.
        int ti = *Tptr;
        float Tf = (ti >= 0 && ti < (1 << 20)) ? (float)ti
                                               : *reinterpret_cast<const float*>(Tptr);
        s = fminf(fmaxf(s, -Tf), Tf);
        out[(size_t)(b0 + tid) * A_ + a] = s;
    }
}

// ---------------------------------------------------------------------------
extern "C" void kernel_launch(void* const* d_in, const int* in_sizes, int n_in,
                              void* d_out, int out_size) {
    const float* x    = (const float*)d_in[0];   // [B, F]
    const float* ta   = (const float*)d_in[1];   // [A, C, 2, F]
    const float* sign = (const float*)d_in[2];   // [A, C]
    const int*   Tptr = (const int*)d_in[3];     // scalar
    float* out = (float*)d_out;                  // [B, A]

    // Pack ta_state: one warp per row, 8 warps/block.
    {
        int rows = TA_ROWS;                       // 102400
        int blocks = (rows + 7) / 8;              // 12800
        pack_ta_kernel<<<blocks, 256>>>(ta);
    }
    // Pack x.
    {
        int blocks = (B_ + 7) / 8;                // 64
        pack_x_kernel<<<blocks, 256>>>(x);
    }
    // Evaluate + vote + clip.
    {
        dim3 grid(A_, B_ / 64);                   // 50 x 8
        eval_kernel<<<grid, 256>>>(sign, Tptr, out);
    }
}

// round 6
// speedup vs baseline: 1.4433x; 1.4433x over previous
#include <cuda_runtime.h>
#include <cstdint>

// Problem constants
#define B_ 512
#define F_ 1180
#define A_ 50
#define C_ 1024
#define W_ 19            // ceil(1180 / 64) u64 words per feature-bitmask
#define W_PAD 20         // padded stride: 160 B, 16-byte aligned for ulonglong2 stores
#define NCLAUSE (A_*C_)  // 51200
#define TA_ROWS (NCLAUSE*2)

// Scratch (allocation-free rule: __device__ globals)
__device__ unsigned long long g_pos[NCLAUSE * W_PAD];  // AoS, full words (survivor path)
__device__ unsigned long long g_neg[NCLAUSE * W_PAD];
__device__ unsigned long long g_pos0[NCLAUSE];         // SoA word 0 (hot path)
__device__ unsigned long long g_neg0[NCLAUSE];
__device__ unsigned long long g_x[B_ * W_PAD];

// ---------------------------------------------------------------------------
// Bit permutation (MUST match between ta pack and x pack):
//   iter it in [0,9): lane loads float4 at it*128 + 4*lane.
//     word 2*it   : bit lane <- v.x,  bit 32+lane <- v.y
//     word 2*it+1 : bit lane <- v.z,  bit 32+lane <- v.w
//   word 18 (tail, 28 floats): bit lane <- row[1152+lane], lane<28; rest 0.
// Rows are 1180*4 = 4720 B = 295*16 B -> float4 loads stay 16B-aligned.
// ---------------------------------------------------------------------------
__global__ void pack_ta_kernel(const float* __restrict__ ta) {
    int warp = (blockIdx.x * blockDim.x + threadIdx.x) >> 5;
    int lane = threadIdx.x & 31;
    if (warp >= TA_ROWS) return;
    const float* row = ta + (size_t)warp * F_;
    const int clause = warp >> 1;
    unsigned long long* out =
        ((warp & 1) ? g_neg : g_pos) + (size_t)clause * W_PAD;
    unsigned long long w0 = 0;
#pragma unroll
    for (int it = 0; it < 9; ++it) {
        float4 v = *reinterpret_cast<const float4*>(row + it * 128 + 4 * lane);
        unsigned a0 = __ballot_sync(0xffffffffu, v.x > 16.0f);
        unsigned a1 = __ballot_sync(0xffffffffu, v.y > 16.0f);
        unsigned b0 = __ballot_sync(0xffffffffu, v.z > 16.0f);
        unsigned b1 = __ballot_sync(0xffffffffu, v.w > 16.0f);
        if (lane == 0) {
            ulonglong2 wd;
            wd.x = (unsigned long long)a0 | ((unsigned long long)a1 << 32);
            wd.y = (unsigned long long)b0 | ((unsigned long long)b1 << 32);
            *reinterpret_cast<ulonglong2*>(out + 2 * it) = wd;  // 16B-aligned (W_PAD even)
            if (it == 0) w0 = wd.x;
        }
    }
    float f = (lane < (F_ - 1152)) ? row[1152 + lane] : -1e9f;
    unsigned bt = __ballot_sync(0xffffffffu, f > 16.0f);
    if (lane == 0) {
        out[18] = (unsigned long long)bt;
        if (warp & 1) g_neg0[clause] = w0;
        else          g_pos0[clause] = w0;
    }
}

__global__ void pack_x_kernel(const float* __restrict__ x) {
    int warp = (blockIdx.x * blockDim.x + threadIdx.x) >> 5;
    int lane = threadIdx.x & 31;
    if (warp >= B_) return;
    const float* row = x + (size_t)warp * F_;
    unsigned long long* out = g_x + (size_t)warp * W_PAD;
#pragma unroll
    for (int it = 0; it < 9; ++it) {
        float4 v = *reinterpret_cast<const float4*>(row + it * 128 + 4 * lane);
        unsigned a0 = __ballot_sync(0xffffffffu, v.x > 0.5f);
        unsigned a1 = __ballot_sync(0xffffffffu, v.y > 0.5f);
        unsigned b0 = __ballot_sync(0xffffffffu, v.z > 0.5f);
        unsigned b1 = __ballot_sync(0xffffffffu, v.w > 0.5f);
        if (lane == 0) {
            ulonglong2 wd;
            wd.x = (unsigned long long)a0 | ((unsigned long long)a1 << 32);
            wd.y = (unsigned long long)b0 | ((unsigned long long)b1 << 32);
            *reinterpret_cast<ulonglong2*>(out + 2 * it) = wd;
        }
    }
    float f = (lane < (F_ - 1152)) ? row[1152 + lane] : -1.0f;
    unsigned bt = __ballot_sync(0xffffffffu, f > 0.5f);
    if (lane == 0) out[18] = (unsigned long long)bt;
}

// ---------------------------------------------------------------------------
// Eval: block = (class a, chunk of 32 batch rows). 8 warps; warp w owns
// clauses [w*128, w*128+128). lane = batch row. Hot path is branch-free:
// word-0 violation test -> survivor bit mask; rare survivors get the exact
// full 19-word check afterwards.
// ---------------------------------------------------------------------------
#define EB 32
__global__ __launch_bounds__(256) void eval_kernel(
    const float* __restrict__ sign,
    const int*   __restrict__ Tptr,
    float*       __restrict__ out)
{
    __shared__ ulonglong2 spn[C_];                  // 16 KB: {pos0, neg0} per clause
    __shared__ unsigned long long sx[EB * W_PAD];   // 5 KB
    __shared__ float sv[8][EB];

    const int a   = blockIdx.x;
    const int b0  = blockIdx.y * EB;
    const int tid = threadIdx.x;

    for (int i = tid; i < C_; i += 256) {
        ulonglong2 pn;
        pn.x = g_pos0[a * C_ + i];
        pn.y = g_neg0[a * C_ + i];
        spn[i] = pn;
    }
    for (int i = tid; i < EB * W_PAD; i += 256)
        sx[i] = g_x[(size_t)b0 * W_PAD + i];
    __syncthreads();

    const int warp = tid >> 5, lane = tid & 31;
    const unsigned long long x0 = sx[lane * W_PAD];
    const int cbase = warp * 128;

    unsigned long long m0 = 0, m1 = 0;   // survivor masks for j 0..63, 64..127
#pragma unroll 4
    for (int j = 0; j < 64; ++j) {
        ulonglong2 pn = spn[cbase + j];
        unsigned long long viol = (pn.x & ~x0) | (pn.y & x0);
        if (viol == 0ull) m0 |= (1ull << j);
    }
#pragma unroll 4
    for (int j = 0; j < 64; ++j) {
        ulonglong2 pn = spn[cbase + 64 + j];
        unsigned long long viol = (pn.x & ~x0) | (pn.y & x0);
        if (viol == 0ull) m1 |= (1ull << j);
    }

    float v = 0.0f;
    // Rare exact path: verify remaining 18 words for each word-0 survivor.
#pragma unroll 1
    for (int half = 0; half < 2; ++half) {
        unsigned long long m = half ? m1 : m0;
        while (m) {
            int j = __ffsll((long long)m) - 1;
            m &= m - 1;
            int c = cbase + half * 64 + j;
            size_t base = ((size_t)a * C_ + c) * W_PAD;
            bool alive = true;
            for (int w = 1; w < W_; ++w) {
                unsigned long long xw = sx[lane * W_PAD + w];
                if ((g_pos[base + w] & ~xw) | (g_neg[base + w] & xw)) {
                    alive = false; break;
                }
            }
            if (alive) v += sign[a * C_ + c];
        }
    }

    sv[warp][lane] = v;
    __syncthreads();

    if (tid < EB) {
        float s = 0.0f;
#pragma unroll
        for (int w = 0; w < 8; ++w) s += sv[w][tid];
        int ti = *Tptr;
        float Tf = (ti >= 0 && ti < (1 << 20)) ? (float)ti
                                               : *reinterpret_cast<const float*>(Tptr);
        s = fminf(fmaxf(s, -Tf), Tf);
        out[(size_t)(b0 + tid) * A_ + a] = s;
    }
}

// ---------------------------------------------------------------------------
extern "C" void kernel_launch(void* const* d_in, const int* in_sizes, int n_in,
                              void* d_out, int out_size) {
    const float* x    = (const float*)d_in[0];   // [B, F]
    const float* ta   = (const float*)d_in[1];   // [A, C, 2, F]
    const float* sign = (const float*)d_in[2];   // [A, C]
    const int*   Tptr = (const int*)d_in[3];     // scalar
    float* out = (float*)d_out;                  // [B, A]

    pack_ta_kernel<<<(TA_ROWS + 7) / 8, 256>>>(ta);          // 12800 blocks
    pack_x_kernel<<<(B_ + 7) / 8, 256>>>(x);                 // 64 blocks
    dim3 grid(A_, B_ / EB);                                  // 50 x 16
    eval_kernel<<<grid, 256>>>(sign, Tptr, out);
}

// round 8
// speedup vs baseline: 1.7687x; 1.2254x over previous
#include <cuda_runtime.h>
#include <cstdint>

// Problem constants
#define B_ 512
#define F_ 1180
#define A_ 50
#define C_ 1024
#define W_ 19            // ceil(1180 / 64) u64 words per feature-bitmask
#define W_PAD 20         // padded stride for g_x
#define NCLAUSE (A_*C_)  // 51200

// Scratch (allocation-free rule: __device__ globals)
__device__ unsigned long long g_x[B_ * W_PAD];   // packed batch rows
__device__ float g_votes[B_ * A_];               // vote accumulator

// ---------------------------------------------------------------------------
// Bit permutation (MUST match between ta pack and x pack):
//   iter it in [0,9): lane loads float4 at it*128 + 4*lane.
//     word 2*it   : bit lane <- v.x,  bit 32+lane <- v.y
//     word 2*it+1 : bit lane <- v.z,  bit 32+lane <- v.w
//   word 18 (tail, 28 floats): bit lane <- row[1152+lane], lane<28; rest 0.
// Rows are 1180*4 = 4720 B = 295*16 B -> float4 loads stay 16B-aligned.
// ---------------------------------------------------------------------------

// Pack binary_features [B,F] and zero the votes buffer.
__global__ void pack_x_kernel(const float* __restrict__ x) {
    // zero votes (grid-stride over 64*256 = 16384 threads, 25600 elems)
    for (int i = blockIdx.x * blockDim.x + threadIdx.x; i < B_ * A_;
         i += gridDim.x * blockDim.x)
        g_votes[i] = 0.0f;

    int warp = (blockIdx.x * blockDim.x + threadIdx.x) >> 5;
    int lane = threadIdx.x & 31;
    if (warp >= B_) return;
    const float* row = x + (size_t)warp * F_;
    unsigned long long* out = g_x + (size_t)warp * W_PAD;
#pragma unroll
    for (int it = 0; it < 9; ++it) {
        float4 v = *reinterpret_cast<const float4*>(row + it * 128 + 4 * lane);
        unsigned a0 = __ballot_sync(0xffffffffu, v.x > 0.5f);
        unsigned a1 = __ballot_sync(0xffffffffu, v.y > 0.5f);
        unsigned b0 = __ballot_sync(0xffffffffu, v.z > 0.5f);
        unsigned b1 = __ballot_sync(0xffffffffu, v.w > 0.5f);
        if (lane == 0) {
            out[2 * it]     = (unsigned long long)a0 | ((unsigned long long)a1 << 32);
            out[2 * it + 1] = (unsigned long long)b0 | ((unsigned long long)b1 << 32);
        }
    }
    float f = (lane < (F_ - 1152)) ? row[1152 + lane] : -1.0f;
    unsigned bt = __ballot_sync(0xffffffffu, f > 0.5f);
    if (lane == 0) out[18] = (unsigned long long)bt;
}

// ---------------------------------------------------------------------------
// Fused pack+eval: one warp per clause. Packs pos & neg rows into smem word
// arrays, then evaluates all 512 batch rows against word 0. Word-0 survivors
// (astronomically rare for random data, but handled exactly) run the full
// 19-word check and atomically add their signed vote.
// ---------------------------------------------------------------------------
#define FW 8   // warps (=clauses) per block
__global__ __launch_bounds__(256) void fused_kernel(
    const float* __restrict__ ta,
    const float* __restrict__ sign)
{
    __shared__ unsigned long long s_pos[FW][W_ + 1];   // +1 pad
    __shared__ unsigned long long s_neg[FW][W_ + 1];
    __shared__ unsigned long long sx0[B_];             // 4 KB: word 0 of each row

    const int tid  = threadIdx.x;
    const int wib  = tid >> 5;
    const int lane = tid & 31;

    // Stage word-0 of all 512 packed batch rows.
    for (int i = tid; i < B_; i += 256)
        sx0[i] = g_x[(size_t)i * W_PAD];

    const int gw = blockIdx.x * FW + wib;    // global clause index
    const int a  = gw / C_;
    const int c  = gw - a * C_;

    // ---- pack both polarity rows of this clause ----
#pragma unroll
    for (int pol = 0; pol < 2; ++pol) {
        const float* row = ta + ((size_t)gw * 2 + pol) * F_;
        unsigned long long* dst = pol ? s_neg[wib] : s_pos[wib];
#pragma unroll
        for (int it = 0; it < 9; ++it) {
            float4 v = *reinterpret_cast<const float4*>(row + it * 128 + 4 * lane);
            unsigned a0 = __ballot_sync(0xffffffffu, v.x > 16.0f);
            unsigned a1 = __ballot_sync(0xffffffffu, v.y > 16.0f);
            unsigned b0 = __ballot_sync(0xffffffffu, v.z > 16.0f);
            unsigned b1 = __ballot_sync(0xffffffffu, v.w > 16.0f);
            if (lane == 0) {
                dst[2 * it]     = (unsigned long long)a0 | ((unsigned long long)a1 << 32);
                dst[2 * it + 1] = (unsigned long long)b0 | ((unsigned long long)b1 << 32);
            }
        }
        float f = (lane < (F_ - 1152)) ? row[1152 + lane] : -1e9f;
        unsigned bt = __ballot_sync(0xffffffffu, f > 16.0f);
        if (lane == 0) dst[18] = (unsigned long long)bt;
    }
    __syncwarp();
    const unsigned long long p0 = s_pos[wib][0];
    const unsigned long long n0 = s_neg[wib][0];

    __syncthreads();   // sx0 ready (also covers the smem word writes)

    // ---- evaluate 512 rows against word 0; lane handles rows lane+32k ----
    unsigned surv = 0;
#pragma unroll
    for (int k = 0; k < 16; ++k) {
        const unsigned long long x0 = sx0[lane + 32 * k];
        if (((p0 & ~x0) | (n0 & x0)) == 0ull) surv |= (1u << k);
    }

    // ---- rare exact path ----
    if (__ballot_sync(0xffffffffu, surv != 0u)) {
        const float sg = sign[a * C_ + c];
        while (surv) {
            const int k = __ffs(surv) - 1;
            surv &= surv - 1;
            const int r = lane + 32 * k;
            bool alive = true;
            for (int w = 1; w < W_; ++w) {
                const unsigned long long xw = g_x[(size_t)r * W_PAD + w];
                if ((s_pos[wib][w] & ~xw) | (s_neg[wib][w] & xw)) {
                    alive = false; break;
                }
            }
            if (alive) atomicAdd(&g_votes[r * A_ + a], sg);
        }
    }
}

// ---------------------------------------------------------------------------
// Epilogue: clip votes into the output.
// ---------------------------------------------------------------------------
__global__ void clip_kernel(const int* __restrict__ Tptr,
                            float* __restrict__ out)
{
    int i = blockIdx.x * blockDim.x + threadIdx.x;
    if (i >= B_ * A_) return;
    int ti = *Tptr;
    float Tf = (ti >= 0 && ti < (1 << 20)) ? (float)ti
                                           : *reinterpret_cast<const float*>(Tptr);
    float s = g_votes[i];
    out[i] = fminf(fmaxf(s, -Tf), Tf);
}

// ---------------------------------------------------------------------------
extern "C" void kernel_launch(void* const* d_in, const int* in_sizes, int n_in,
                              void* d_out, int out_size) {
    const float* x    = (const float*)d_in[0];   // [B, F]
    const float* ta   = (const float*)d_in[1];   // [A, C, 2, F]
    const float* sign = (const float*)d_in[2];   // [A, C]
    const int*   Tptr = (const int*)d_in[3];     // scalar
    float* out = (float*)d_out;                  // [B, A]

    pack_x_kernel<<<64, 256>>>(x);                       // pack x + zero votes
    fused_kernel<<<NCLAUSE / FW, 256>>>(ta, sign);       // 6400 blocks
    clip_kernel<<<(B_ * A_ + 255) / 256, 256>>>(Tptr, out);
}

// round 9
// speedup vs baseline: 1.7842x; 1.0088x over previous
#include <cuda_runtime.h>
#include <cstdint>

// Problem constants
#define B_ 512
#define F_ 1180
#define A_ 50
#define C_ 1024
#define W_ 19            // ceil(1180 / 64) u64 words per feature-bitmask
#define W_PAD 20         // padded stride for g_x
#define NCLAUSE (A_*C_)  // 51200

// Scratch (allocation-free rule: __device__ globals)
__device__ unsigned long long g_x[B_ * W_PAD];   // packed batch rows
__device__ float g_votes[B_ * A_];               // vote accumulator

// ---------------------------------------------------------------------------
// Bit permutation (MUST match between ta pack and x pack):
//   iter it in [0,9): lane loads float4 at it*128 + 4*lane.
//     word 2*it   : bit lane <- v.x,  bit 32+lane <- v.y
//     word 2*it+1 : bit lane <- v.z,  bit 32+lane <- v.w
//   word 18 (tail, 28 floats): bit lane <- row[1152+lane], lane<28; rest 0.
// Rows are 1180*4 = 4720 B = 295*16 B -> float4 loads stay 16B-aligned.
// ---------------------------------------------------------------------------

// Pack binary_features [B,F] (one warp per block = one row) + zero votes.
__global__ __launch_bounds__(32) void pack_x_kernel(const float* __restrict__ x) {
    const int lane = threadIdx.x;
    const int row_id = blockIdx.x;

    // zero votes: 512 blocks x 32 lanes = 16384 threads over 25600 elems
    for (int i = row_id * 32 + lane; i < B_ * A_; i += gridDim.x * 32)
        g_votes[i] = 0.0f;

    const float* row = x + (size_t)row_id * F_;
    unsigned long long* out = g_x + (size_t)row_id * W_PAD;

    // Issue all 9 float4 loads up front (deep MLP), then ballot.
    float4 v[9];
#pragma unroll
    for (int it = 0; it < 9; ++it)
        v[it] = *reinterpret_cast<const float4*>(row + it * 128 + 4 * lane);
    float ftail = (lane < (F_ - 1152)) ? row[1152 + lane] : -1.0f;

#pragma unroll
    for (int it = 0; it < 9; ++it) {
        unsigned a0 = __ballot_sync(0xffffffffu, v[it].x > 0.5f);
        unsigned a1 = __ballot_sync(0xffffffffu, v[it].y > 0.5f);
        unsigned b0 = __ballot_sync(0xffffffffu, v[it].z > 0.5f);
        unsigned b1 = __ballot_sync(0xffffffffu, v[it].w > 0.5f);
        if (lane == 0) {
            out[2 * it]     = (unsigned long long)a0 | ((unsigned long long)a1 << 32);
            out[2 * it + 1] = (unsigned long long)b0 | ((unsigned long long)b1 << 32);
        }
    }
    unsigned bt = __ballot_sync(0xffffffffu, ftail > 0.5f);
    if (lane == 0) out[18] = (unsigned long long)bt;
}

// ---------------------------------------------------------------------------
// Fused pack+eval: one warp per clause. Packs pos & neg rows into smem word
// arrays, then evaluates all 512 batch rows against word 0. Word-0 survivors
// (astronomically rare for random data, but handled exactly) run the full
// 19-word check and atomically add their signed vote.
// ---------------------------------------------------------------------------
#define FW 8   // warps (=clauses) per block
__global__ __launch_bounds__(256) void fused_kernel(
    const float* __restrict__ ta,
    const float* __restrict__ sign)
{
    __shared__ unsigned long long s_pos[FW][W_ + 1];   // +1 pad
    __shared__ unsigned long long s_neg[FW][W_ + 1];
    __shared__ unsigned long long sx0[B_];             // 4 KB: word 0 of each row

    const int tid  = threadIdx.x;
    const int wib  = tid >> 5;
    const int lane = tid & 31;

    // Stage word-0 of all 512 packed batch rows.
    for (int i = tid; i < B_; i += 256)
        sx0[i] = g_x[(size_t)i * W_PAD];

    const int gw = blockIdx.x * FW + wib;    // global clause index
    const int a  = gw / C_;
    const int c  = gw - a * C_;

    const float* rowp = ta + ((size_t)gw * 2) * F_;       // pos row
    const float* rown = rowp + F_;                        // neg row

    // ---- pack both polarity rows, interleaved 2-deep for MLP ----
#pragma unroll
    for (int it = 0; it < 9; ++it) {
        float4 vp = *reinterpret_cast<const float4*>(rowp + it * 128 + 4 * lane);
        float4 vn = *reinterpret_cast<const float4*>(rown + it * 128 + 4 * lane);
        unsigned pa0 = __ballot_sync(0xffffffffu, vp.x > 16.0f);
        unsigned pa1 = __ballot_sync(0xffffffffu, vp.y > 16.0f);
        unsigned pb0 = __ballot_sync(0xffffffffu, vp.z > 16.0f);
        unsigned pb1 = __ballot_sync(0xffffffffu, vp.w > 16.0f);
        unsigned na0 = __ballot_sync(0xffffffffu, vn.x > 16.0f);
        unsigned na1 = __ballot_sync(0xffffffffu, vn.y > 16.0f);
        unsigned nb0 = __ballot_sync(0xffffffffu, vn.z > 16.0f);
        unsigned nb1 = __ballot_sync(0xffffffffu, vn.w > 16.0f);
        if (lane == 0) {
            s_pos[wib][2 * it]     = (unsigned long long)pa0 | ((unsigned long long)pa1 << 32);
            s_pos[wib][2 * it + 1] = (unsigned long long)pb0 | ((unsigned long long)pb1 << 32);
            s_neg[wib][2 * it]     = (unsigned long long)na0 | ((unsigned long long)na1 << 32);
            s_neg[wib][2 * it + 1] = (unsigned long long)nb0 | ((unsigned long long)nb1 << 32);
        }
    }
    {
        float fp = (lane < (F_ - 1152)) ? rowp[1152 + lane] : -1e9f;
        float fn = (lane < (F_ - 1152)) ? rown[1152 + lane] : -1e9f;
        unsigned btp = __ballot_sync(0xffffffffu, fp > 16.0f);
        unsigned btn = __ballot_sync(0xffffffffu, fn > 16.0f);
        if (lane == 0) {
            s_pos[wib][18] = (unsigned long long)btp;
            s_neg[wib][18] = (unsigned long long)btn;
        }
    }
    __syncwarp();
    const unsigned long long p0 = s_pos[wib][0];
    const unsigned long long n0 = s_neg[wib][0];

    __syncthreads();   // sx0 ready (also covers the smem word writes)

    // ---- evaluate 512 rows against word 0; lane handles rows lane+32k ----
    unsigned surv = 0;
#pragma unroll
    for (int k = 0; k < 16; ++k) {
        const unsigned long long x0 = sx0[lane + 32 * k];
        if (((p0 & ~x0) | (n0 & x0)) == 0ull) surv |= (1u << k);
    }

    // ---- rare exact path ----
    if (__ballot_sync(0xffffffffu, surv != 0u)) {
        const float sg = sign[a * C_ + c];
        while (surv) {
            const int k = __ffs(surv) - 1;
            surv &= surv - 1;
            const int r = lane + 32 * k;
            bool alive = true;
            for (int w = 1; w < W_; ++w) {
                const unsigned long long xw = g_x[(size_t)r * W_PAD + w];
                if ((s_pos[wib][w] & ~xw) | (s_neg[wib][w] & xw)) {
                    alive = false; break;
                }
            }
            if (alive) atomicAdd(&g_votes[r * A_ + a], sg);
        }
    }
}

// ---------------------------------------------------------------------------
// Epilogue: clip votes into the output.
// ---------------------------------------------------------------------------
__global__ void clip_kernel(const int* __restrict__ Tptr,
                            float* __restrict__ out)
{
    int i = blockIdx.x * blockDim.x + threadIdx.x;
    if (i >= B_ * A_) return;
    int ti = *Tptr;
    float Tf = (ti >= 0 && ti < (1 << 20)) ? (float)ti
                                           : *reinterpret_cast<const float*>(Tptr);
    float s = g_votes[i];
    out[i] = fminf(fmaxf(s, -Tf), Tf);
}

// ---------------------------------------------------------------------------
extern "C" void kernel_launch(void* const* d_in, const int* in_sizes, int n_in,
                              void* d_out, int out_size) {
    const float* x    = (const float*)d_in[0];   // [B, F]
    const float* ta   = (const float*)d_in[1];   // [A, C, 2, F]
    const float* sign = (const float*)d_in[2];   // [A, C]
    const int*   Tptr = (const int*)d_in[3];     // scalar
    float* out = (float*)d_out;                  // [B, A]

    pack_x_kernel<<<B_, 32>>>(x);                        // 512 blocks, 1 warp each
    fused_kernel<<<NCLAUSE / FW, 256>>>(ta, sign);       // 6400 blocks
    clip_kernel<<<(B_ * A_ + 255) / 256, 256>>>(Tptr, out);
}